// round 1
// baseline (speedup 1.0000x reference)
#include <cuda_runtime.h>

#define HH 96
#define WW 96
#define NPIX 9216
#define NHEADS 8
#define HD 16
#define HSUB 48
#define NKEY (HSUB*HSUB)

// Scratch (device globals; no allocations allowed)
__device__ __align__(16) float g_q[NHEADS * NPIX * HD];   // [head][pix][16]
__device__ __align__(16) float g_k[NHEADS * NKEY * HD];   // [head][48*48][16] (even rows/cols only)
__device__ __align__(16) float g_v[NHEADS * NKEY * HD];
__device__ __align__(16) float g_att[NPIX * 128];         // [pix][channel]

// ---------------------------------------------------------------------------
// Kernel 1: grouped 3x3 conv (depthwise-style, O=384, G=128 => out o uses in o/3)
// Routes q (scaled by 0.25) and k/v (even pixels only, 48x48 grid).
// ---------------------------------------------------------------------------
__global__ void conv_qkv_kernel(const float* __restrict__ x,
                                const float* __restrict__ wq,
                                const float* __restrict__ bq) {
    __shared__ float xs[98 * 98];
    const int ic = blockIdx.x;
    const int tid = threadIdx.x;

    for (int idx = tid; idx < 98 * 98; idx += 256) xs[idx] = 0.f;
    __syncthreads();
    const float* xp = x + ic * NPIX;
    for (int idx = tid; idx < NPIX; idx += 256) {
        int i = idx / 96, j = idx - i * 96;
        xs[(i + 1) * 98 + (j + 1)] = xp[idx];
    }
    __syncthreads();

    #pragma unroll
    for (int r = 0; r < 3; r++) {
        const int o = ic * 3 + r;
        const float* wp = wq + o * 9;
        const float w0 = wp[0], w1 = wp[1], w2 = wp[2];
        const float w3 = wp[3], w4 = wp[4], w5 = wp[5];
        const float w6 = wp[6], w7 = wp[7], w8 = wp[8];
        const float bb = bq[o];
        const int t = o / 128;       // 0=q, 1=k, 2=v
        const int c = o - t * 128;
        const int n = c >> 4;
        const int d = c & 15;

        for (int idx = tid; idx < NPIX; idx += 256) {
            int i = idx / 96, j = idx - i * 96;
            const float* p0 = &xs[i * 98 + j];
            float acc = bb;
            acc = fmaf(w0, p0[0],   acc);
            acc = fmaf(w1, p0[1],   acc);
            acc = fmaf(w2, p0[2],   acc);
            acc = fmaf(w3, p0[98],  acc);
            acc = fmaf(w4, p0[99],  acc);
            acc = fmaf(w5, p0[100], acc);
            acc = fmaf(w6, p0[196], acc);
            acc = fmaf(w7, p0[197], acc);
            acc = fmaf(w8, p0[198], acc);
            if (t == 0) {
                g_q[(n * NPIX + idx) * HD + d] = acc * 0.25f;  // HD^-0.5 = 0.25
            } else if (((i | j) & 1) == 0) {
                int kidx = (n * NKEY + (i >> 1) * HSUB + (j >> 1)) * HD + d;
                if (t == 1) g_k[kidx] = acc;
                else        g_v[kidx] = acc;
            }
        }
    }
}

// ---------------------------------------------------------------------------
// Kernel 2: neighborhood attention.
// grid (6,6,8): CTA = (col-tile, row-tile, head), 16x16 queries per CTA,
// 16x16 key tile of the 48x48 subsampled grid in SMEM (stride 5 float4 =
// 80B per key -> conflict-free LDS.128).
// ---------------------------------------------------------------------------
__device__ __forceinline__ float dot16(float4 q0, float4 q1, float4 q2, float4 q3,
                                       const float4* kp) {
    float4 a = kp[0], b = kp[1], c = kp[2], d = kp[3];
    float s = q0.x * a.x;
    s = fmaf(q0.y, a.y, s); s = fmaf(q0.z, a.z, s); s = fmaf(q0.w, a.w, s);
    s = fmaf(q1.x, b.x, s); s = fmaf(q1.y, b.y, s); s = fmaf(q1.z, b.z, s); s = fmaf(q1.w, b.w, s);
    s = fmaf(q2.x, c.x, s); s = fmaf(q2.y, c.y, s); s = fmaf(q2.z, c.z, s); s = fmaf(q2.w, c.w, s);
    s = fmaf(q3.x, d.x, s); s = fmaf(q3.y, d.y, s); s = fmaf(q3.z, d.z, s); s = fmaf(q3.w, d.w, s);
    return s;
}

__global__ void attn_kernel() {
    __shared__ float4 Kt[256 * 5];
    __shared__ float4 Vt[256 * 5];
    const int tj = blockIdx.x, ti = blockIdx.y, n = blockIdx.z;
    const int tid = threadIdx.x;

    const int si0 = min(max(ti * 8 - 3, 0), 40);
    const int sj0 = min(max(tj * 8 - 3, 0), 40);

    // Load 16x16 key/value tile (one key per thread)
    {
        int kr = tid >> 4, kc = tid & 15;
        int gr = min(si0 + kr, 47);
        int gc = min(sj0 + kc, 47);
        const float4* kg = (const float4*)g_k + (size_t)(n * NKEY + gr * HSUB + gc) * 4;
        const float4* vg = (const float4*)g_v + (size_t)(n * NKEY + gr * HSUB + gc) * 4;
        #pragma unroll
        for (int e = 0; e < 4; e++) {
            Kt[tid * 5 + e] = kg[e];
            Vt[tid * 5 + e] = vg[e];
        }
    }
    __syncthreads();

    const int qil = tid >> 4, qjl = tid & 15;
    const int qi = ti * 16 + qil;
    const int qj = tj * 16 + qjl;
    const int reli = min(max((qi >> 1) - 3, 0), 40) - si0;
    const int relj = min(max((qj >> 1) - 3, 0), 40) - sj0;

    const float4* qg = (const float4*)g_q + (size_t)(n * NPIX + qi * 96 + qj) * 4;
    const float4 q0 = qg[0], q1 = qg[1], q2 = qg[2], q3 = qg[3];

    float lg[64];
    float mx = -3.4e38f;
    #pragma unroll
    for (int p = 0; p < 8; p++) {
        const int rb = (reli + p) * 16 + relj;
        #pragma unroll
        for (int cc = 0; cc < 8; cc++) {
            float s = dot16(q0, q1, q2, q3, &Kt[(rb + cc) * 5]);
            lg[p * 8 + cc] = s;
            mx = fmaxf(mx, s);
        }
    }

    float sum = 0.f;
    #pragma unroll
    for (int k = 0; k < 64; k++) {
        float e = __expf(lg[k] - mx);
        lg[k] = e;
        sum += e;
    }

    float4 a0 = {0.f, 0.f, 0.f, 0.f};
    float4 a1 = a0, a2 = a0, a3 = a0;
    #pragma unroll
    for (int p = 0; p < 8; p++) {
        const int rb = (reli + p) * 16 + relj;
        #pragma unroll
        for (int cc = 0; cc < 8; cc++) {
            const float wv = lg[p * 8 + cc];
            const float4* vp = &Vt[(rb + cc) * 5];
            float4 v0 = vp[0], v1 = vp[1], v2 = vp[2], v3 = vp[3];
            a0.x = fmaf(wv, v0.x, a0.x); a0.y = fmaf(wv, v0.y, a0.y);
            a0.z = fmaf(wv, v0.z, a0.z); a0.w = fmaf(wv, v0.w, a0.w);
            a1.x = fmaf(wv, v1.x, a1.x); a1.y = fmaf(wv, v1.y, a1.y);
            a1.z = fmaf(wv, v1.z, a1.z); a1.w = fmaf(wv, v1.w, a1.w);
            a2.x = fmaf(wv, v2.x, a2.x); a2.y = fmaf(wv, v2.y, a2.y);
            a2.z = fmaf(wv, v2.z, a2.z); a2.w = fmaf(wv, v2.w, a2.w);
            a3.x = fmaf(wv, v3.x, a3.x); a3.y = fmaf(wv, v3.y, a3.y);
            a3.z = fmaf(wv, v3.z, a3.z); a3.w = fmaf(wv, v3.w, a3.w);
        }
    }

    const float inv = 1.f / sum;
    a0.x *= inv; a0.y *= inv; a0.z *= inv; a0.w *= inv;
    a1.x *= inv; a1.y *= inv; a1.z *= inv; a1.w *= inv;
    a2.x *= inv; a2.y *= inv; a2.z *= inv; a2.w *= inv;
    a3.x *= inv; a3.y *= inv; a3.z *= inv; a3.w *= inv;

    float4* og = (float4*)g_att + (size_t)(qi * 96 + qj) * 32 + n * 4;
    og[0] = a0; og[1] = a1; og[2] = a2; og[3] = a3;
}

// ---------------------------------------------------------------------------
// Kernel 3: 1x1 projection GEMM. out[o][pix] = sum_c W[o][c]*att[pix][c] + b[o]
// CTA: 64 pixels x 128 outs. K=128 in two 64-chunks (SMEM = exactly 48KB).
// Thread tile 4 pix x 8 out.
// ---------------------------------------------------------------------------
__global__ void proj_kernel(const float* __restrict__ pw,
                            const float* __restrict__ pb,
                            float* __restrict__ out) {
    __shared__ __align__(16) float As[64 * 64];    // [k][pix]
    __shared__ __align__(16) float Bs[64 * 128];   // [k][o]
    const int pix0 = blockIdx.x * 64;
    const int tid = threadIdx.x;
    const int tp = tid >> 4;       // pixel group 0..15
    const int tout = tid & 15;     // out group 0..15

    float acc[4][8];
    #pragma unroll
    for (int pp = 0; pp < 4; pp++)
        #pragma unroll
        for (int oo = 0; oo < 8; oo++) acc[pp][oo] = 0.f;

    for (int kt = 0; kt < 2; kt++) {
        __syncthreads();
        {
            int p = tid & 63, k4 = tid >> 6;   // k4 in 0..3
            const float4* src = (const float4*)g_att + (size_t)(pix0 + p) * 32 + kt * 16;
            #pragma unroll
            for (int r2 = 0; r2 < 4; r2++) {
                int kk = k4 + 4 * r2;          // 0..15
                float4 v = src[kk];
                As[(kk * 4 + 0) * 64 + p] = v.x;
                As[(kk * 4 + 1) * 64 + p] = v.y;
                As[(kk * 4 + 2) * 64 + p] = v.z;
                As[(kk * 4 + 3) * 64 + p] = v.w;
            }
        }
        {
            int o = tid & 127, g = tid >> 7;   // g in 0..1
            const float4* src = (const float4*)pw + (size_t)o * 32 + kt * 16;
            #pragma unroll
            for (int r2 = 0; r2 < 8; r2++) {
                int kk = g + 2 * r2;           // 0..15
                float4 v = src[kk];
                Bs[(kk * 4 + 0) * 128 + o] = v.x;
                Bs[(kk * 4 + 1) * 128 + o] = v.y;
                Bs[(kk * 4 + 2) * 128 + o] = v.z;
                Bs[(kk * 4 + 3) * 128 + o] = v.w;
            }
        }
        __syncthreads();

        #pragma unroll 8
        for (int k = 0; k < 64; k++) {
            float4 a  = ((const float4*)As)[k * 16 + tp];
            float4 b0 = ((const float4*)Bs)[k * 32 + tout * 2];
            float4 b1 = ((const float4*)Bs)[k * 32 + tout * 2 + 1];
            float av[4] = {a.x, a.y, a.z, a.w};
            float bv[8] = {b0.x, b0.y, b0.z, b0.w, b1.x, b1.y, b1.z, b1.w};
            #pragma unroll
            for (int pp = 0; pp < 4; pp++)
                #pragma unroll
                for (int oo = 0; oo < 8; oo++)
                    acc[pp][oo] = fmaf(av[pp], bv[oo], acc[pp][oo]);
        }
    }

    #pragma unroll
    for (int oo = 0; oo < 8; oo++) {
        int o = tout * 8 + oo;
        float bias = pb[o];
        float4 r = make_float4(acc[0][oo] + bias, acc[1][oo] + bias,
                               acc[2][oo] + bias, acc[3][oo] + bias);
        *(float4*)(out + (size_t)o * NPIX + pix0 + tp * 4) = r;
    }
}

// ---------------------------------------------------------------------------
extern "C" void kernel_launch(void* const* d_in, const int* in_sizes, int n_in,
                              void* d_out, int out_size) {
    const float* x      = (const float*)d_in[0];
    const float* qkv_w  = (const float*)d_in[1];
    const float* qkv_b  = (const float*)d_in[2];
    const float* proj_w = (const float*)d_in[3];
    const float* proj_b = (const float*)d_in[4];
    float* out = (float*)d_out;

    conv_qkv_kernel<<<128, 256>>>(x, qkv_w, qkv_b);
    attn_kernel<<<dim3(6, 6, NHEADS), 256>>>();
    proj_kernel<<<144, 256>>>(proj_w, proj_b, out);
}

// round 2
// speedup vs baseline: 1.0941x; 1.0941x over previous
#include <cuda_runtime.h>

#define HH 96
#define WW 96
#define NPIX 9216
#define NHEADS 8
#define HD 16
#define HSUB 48
#define NKEY (HSUB*HSUB)

// Scratch (device globals; no allocations allowed)
__device__ __align__(16) float g_q[NHEADS * NPIX * HD];   // [head][pix][16]
__device__ __align__(16) float g_k[NHEADS * NKEY * HD];   // [head][48*48][16] (even rows/cols only)
__device__ __align__(16) float g_v[NHEADS * NKEY * HD];
__device__ __align__(16) float g_att[NPIX * 128];         // [pix][channel]

// ---------------------------------------------------------------------------
// Kernel 1: grouped 3x3 conv. Grid (6 row-tiles, 128 channels), 384 threads.
// Each CTA: 16 rows x 96 cols of one input channel -> 3 outputs (q/k/v route).
// 18x98 SMEM halo tile; 9-point stencil loaded once, reused for 3 outputs.
// ---------------------------------------------------------------------------
__global__ __launch_bounds__(384) void conv_qkv_kernel(
        const float* __restrict__ x,
        const float* __restrict__ wq,
        const float* __restrict__ bq) {
    __shared__ float xs[18 * 98];
    const int i0 = blockIdx.x * 16;      // first output row of tile
    const int ic = blockIdx.y;           // input channel
    const int tid = threadIdx.x;

    // Load 18 rows (i0-1 .. i0+16), 96 cols; zero-pad cols 0/97 and OOB rows.
    {
        const float* xp = x + (size_t)ic * NPIX;
        for (int idx = tid; idx < 18 * 96; idx += 384) {
            int r = idx / 96, c = idx - r * 96;
            int gi = i0 - 1 + r;
            float v = (gi >= 0 && gi < 96) ? xp[gi * 96 + c] : 0.f;
            xs[r * 98 + c + 1] = v;
        }
        if (tid < 18) { xs[tid * 98] = 0.f; xs[tid * 98 + 97] = 0.f; }
    }
    __syncthreads();

    // Per-thread pixel lanes: 4 rows x 96 cols, stride 4 rows, 4 iterations.
    const int r0 = tid / 96;             // 0..3
    const int j  = tid - r0 * 96;        // 0..95

    // Hoist per-output routing + weights.
    float w[3][9], bb[3];
    int   t[3], n[3], d[3];
    #pragma unroll
    for (int r = 0; r < 3; r++) {
        const int o = ic * 3 + r;
        const float* wp = wq + o * 9;
        #pragma unroll
        for (int e = 0; e < 9; e++) w[r][e] = wp[e];
        bb[r] = bq[o];
        t[r] = o >> 7;                   // 0=q,1=k,2=v
        int c = o & 127;
        n[r] = c >> 4;
        d[r] = c & 15;
    }

    #pragma unroll
    for (int rr = 0; rr < 4; rr++) {
        const int il = rr * 4 + r0;      // local row 0..15
        const int i  = i0 + il;          // global row
        const float* p0 = &xs[il * 98 + j];
        const float v0 = p0[0],   v1 = p0[1],   v2 = p0[2];
        const float v3 = p0[98],  v4 = p0[99],  v5 = p0[100];
        const float v6 = p0[196], v7 = p0[197], v8 = p0[198];
        const int idx = i * 96 + j;
        const bool even = ((i | j) & 1) == 0;
        const int kpix = (i >> 1) * HSUB + (j >> 1);

        #pragma unroll
        for (int r = 0; r < 3; r++) {
            float acc = bb[r];
            acc = fmaf(w[r][0], v0, acc);
            acc = fmaf(w[r][1], v1, acc);
            acc = fmaf(w[r][2], v2, acc);
            acc = fmaf(w[r][3], v3, acc);
            acc = fmaf(w[r][4], v4, acc);
            acc = fmaf(w[r][5], v5, acc);
            acc = fmaf(w[r][6], v6, acc);
            acc = fmaf(w[r][7], v7, acc);
            acc = fmaf(w[r][8], v8, acc);
            if (t[r] == 0) {
                g_q[((size_t)n[r] * NPIX + idx) * HD + d[r]] = acc * 0.25f;
            } else if (even) {
                size_t kidx = ((size_t)n[r] * NKEY + kpix) * HD + d[r];
                if (t[r] == 1) g_k[kidx] = acc;
                else           g_v[kidx] = acc;
            }
        }
    }
}

// ---------------------------------------------------------------------------
// Kernel 2: neighborhood attention.
// grid (6,6,8): CTA = (col-tile, row-tile, head), 16x16 queries per CTA,
// 16x16 key tile of the 48x48 subsampled grid in SMEM (stride 5 float4 =
// 80B per key -> conflict-free LDS.128).
// ---------------------------------------------------------------------------
__device__ __forceinline__ float dot16(float4 q0, float4 q1, float4 q2, float4 q3,
                                       const float4* kp) {
    float4 a = kp[0], b = kp[1], c = kp[2], d = kp[3];
    float s = q0.x * a.x;
    s = fmaf(q0.y, a.y, s); s = fmaf(q0.z, a.z, s); s = fmaf(q0.w, a.w, s);
    s = fmaf(q1.x, b.x, s); s = fmaf(q1.y, b.y, s); s = fmaf(q1.z, b.z, s); s = fmaf(q1.w, b.w, s);
    s = fmaf(q2.x, c.x, s); s = fmaf(q2.y, c.y, s); s = fmaf(q2.z, c.z, s); s = fmaf(q2.w, c.w, s);
    s = fmaf(q3.x, d.x, s); s = fmaf(q3.y, d.y, s); s = fmaf(q3.z, d.z, s); s = fmaf(q3.w, d.w, s);
    return s;
}

__global__ __launch_bounds__(256) void attn_kernel() {
    __shared__ float4 Kt[256 * 5];
    __shared__ float4 Vt[256 * 5];
    const int tj = blockIdx.x, ti = blockIdx.y, n = blockIdx.z;
    const int tid = threadIdx.x;

    const int si0 = min(max(ti * 8 - 3, 0), 40);
    const int sj0 = min(max(tj * 8 - 3, 0), 40);

    // Load 16x16 key/value tile (one key per thread)
    {
        int kr = tid >> 4, kc = tid & 15;
        int gr = min(si0 + kr, 47);
        int gc = min(sj0 + kc, 47);
        const float4* kg = (const float4*)g_k + (size_t)(n * NKEY + gr * HSUB + gc) * 4;
        const float4* vg = (const float4*)g_v + (size_t)(n * NKEY + gr * HSUB + gc) * 4;
        #pragma unroll
        for (int e = 0; e < 4; e++) {
            Kt[tid * 5 + e] = kg[e];
            Vt[tid * 5 + e] = vg[e];
        }
    }
    __syncthreads();

    const int qil = tid >> 4, qjl = tid & 15;
    const int qi = ti * 16 + qil;
    const int qj = tj * 16 + qjl;
    const int reli = min(max((qi >> 1) - 3, 0), 40) - si0;
    const int relj = min(max((qj >> 1) - 3, 0), 40) - sj0;

    const float4* qg = (const float4*)g_q + (size_t)(n * NPIX + qi * 96 + qj) * 4;
    const float4 q0 = qg[0], q1 = qg[1], q2 = qg[2], q3 = qg[3];

    float lg[64];
    float mx = -3.4e38f;
    #pragma unroll
    for (int p = 0; p < 8; p++) {
        const int rb = (reli + p) * 16 + relj;
        #pragma unroll
        for (int cc = 0; cc < 8; cc++) {
            float s = dot16(q0, q1, q2, q3, &Kt[(rb + cc) * 5]);
            lg[p * 8 + cc] = s;
            mx = fmaxf(mx, s);
        }
    }

    float sum = 0.f;
    #pragma unroll
    for (int k = 0; k < 64; k++) {
        float e = __expf(lg[k] - mx);
        lg[k] = e;
        sum += e;
    }

    float4 a0 = {0.f, 0.f, 0.f, 0.f};
    float4 a1 = a0, a2 = a0, a3 = a0;
    #pragma unroll
    for (int p = 0; p < 8; p++) {
        const int rb = (reli + p) * 16 + relj;
        #pragma unroll
        for (int cc = 0; cc < 8; cc++) {
            const float wv = lg[p * 8 + cc];
            const float4* vp = &Vt[(rb + cc) * 5];
            float4 v0 = vp[0], v1 = vp[1], v2 = vp[2], v3 = vp[3];
            a0.x = fmaf(wv, v0.x, a0.x); a0.y = fmaf(wv, v0.y, a0.y);
            a0.z = fmaf(wv, v0.z, a0.z); a0.w = fmaf(wv, v0.w, a0.w);
            a1.x = fmaf(wv, v1.x, a1.x); a1.y = fmaf(wv, v1.y, a1.y);
            a1.z = fmaf(wv, v1.z, a1.z); a1.w = fmaf(wv, v1.w, a1.w);
            a2.x = fmaf(wv, v2.x, a2.x); a2.y = fmaf(wv, v2.y, a2.y);
            a2.z = fmaf(wv, v2.z, a2.z); a2.w = fmaf(wv, v2.w, a2.w);
            a3.x = fmaf(wv, v3.x, a3.x); a3.y = fmaf(wv, v3.y, a3.y);
            a3.z = fmaf(wv, v3.z, a3.z); a3.w = fmaf(wv, v3.w, a3.w);
        }
    }

    const float inv = 1.f / sum;
    a0.x *= inv; a0.y *= inv; a0.z *= inv; a0.w *= inv;
    a1.x *= inv; a1.y *= inv; a1.z *= inv; a1.w *= inv;
    a2.x *= inv; a2.y *= inv; a2.z *= inv; a2.w *= inv;
    a3.x *= inv; a3.y *= inv; a3.z *= inv; a3.w *= inv;

    float4* og = (float4*)g_att + (size_t)(qi * 96 + qj) * 32 + n * 4;
    og[0] = a0; og[1] = a1; og[2] = a2; og[3] = a3;
}

// ---------------------------------------------------------------------------
// Kernel 3: 1x1 projection GEMM. out[o][pix] = sum_c W[o][c]*att[pix][c] + b[o]
// CTA: 64 pixels x 128 outs. K=128 in two 64-chunks (SMEM = exactly 48KB).
// Thread tile 4 pix x 8 out.
// ---------------------------------------------------------------------------
__global__ __launch_bounds__(256) void proj_kernel(
        const float* __restrict__ pw,
        const float* __restrict__ pb,
        float* __restrict__ out) {
    __shared__ __align__(16) float As[64 * 64];    // [k][pix]
    __shared__ __align__(16) float Bs[64 * 128];   // [k][o]
    const int pix0 = blockIdx.x * 64;
    const int tid = threadIdx.x;
    const int tp = tid >> 4;       // pixel group 0..15
    const int tout = tid & 15;     // out group 0..15

    float acc[4][8];
    #pragma unroll
    for (int pp = 0; pp < 4; pp++)
        #pragma unroll
        for (int oo = 0; oo < 8; oo++) acc[pp][oo] = 0.f;

    for (int kt = 0; kt < 2; kt++) {
        __syncthreads();
        {
            int p = tid & 63, k4 = tid >> 6;   // k4 in 0..3
            const float4* src = (const float4*)g_att + (size_t)(pix0 + p) * 32 + kt * 16;
            #pragma unroll
            for (int r2 = 0; r2 < 4; r2++) {
                int kk = k4 + 4 * r2;          // 0..15
                float4 v = src[kk];
                As[(kk * 4 + 0) * 64 + p] = v.x;
                As[(kk * 4 + 1) * 64 + p] = v.y;
                As[(kk * 4 + 2) * 64 + p] = v.z;
                As[(kk * 4 + 3) * 64 + p] = v.w;
            }
        }
        {
            int o = tid & 127, g = tid >> 7;   // g in 0..1
            const float4* src = (const float4*)pw + (size_t)o * 32 + kt * 16;
            #pragma unroll
            for (int r2 = 0; r2 < 8; r2++) {
                int kk = g + 2 * r2;           // 0..15
                float4 v = src[kk];
                Bs[(kk * 4 + 0) * 128 + o] = v.x;
                Bs[(kk * 4 + 1) * 128 + o] = v.y;
                Bs[(kk * 4 + 2) * 128 + o] = v.z;
                Bs[(kk * 4 + 3) * 128 + o] = v.w;
            }
        }
        __syncthreads();

        #pragma unroll 8
        for (int k = 0; k < 64; k++) {
            float4 a  = ((const float4*)As)[k * 16 + tp];
            float4 b0 = ((const float4*)Bs)[k * 32 + tout * 2];
            float4 b1 = ((const float4*)Bs)[k * 32 + tout * 2 + 1];
            float av[4] = {a.x, a.y, a.z, a.w};
            float bv[8] = {b0.x, b0.y, b0.z, b0.w, b1.x, b1.y, b1.z, b1.w};
            #pragma unroll
            for (int pp = 0; pp < 4; pp++)
                #pragma unroll
                for (int oo = 0; oo < 8; oo++)
                    acc[pp][oo] = fmaf(av[pp], bv[oo], acc[pp][oo]);
        }
    }

    #pragma unroll
    for (int oo = 0; oo < 8; oo++) {
        int o = tout * 8 + oo;
        float bias = pb[o];
        float4 r = make_float4(acc[0][oo] + bias, acc[1][oo] + bias,
                               acc[2][oo] + bias, acc[3][oo] + bias);
        *(float4*)(out + (size_t)o * NPIX + pix0 + tp * 4) = r;
    }
}

// ---------------------------------------------------------------------------
extern "C" void kernel_launch(void* const* d_in, const int* in_sizes, int n_in,
                              void* d_out, int out_size) {
    const float* x      = (const float*)d_in[0];
    const float* qkv_w  = (const float*)d_in[1];
    const float* qkv_b  = (const float*)d_in[2];
    const float* proj_w = (const float*)d_in[3];
    const float* proj_b = (const float*)d_in[4];
    float* out = (float*)d_out;

    conv_qkv_kernel<<<dim3(6, 128), 384>>>(x, qkv_w, qkv_b);
    attn_kernel<<<dim3(6, 6, NHEADS), 256>>>();
    proj_kernel<<<144, 256>>>(proj_w, proj_b, out);
}

// round 4
// speedup vs baseline: 1.1433x; 1.0449x over previous
#include <cuda_runtime.h>

#define HH 96
#define WW 96
#define NPIX 9216
#define NHEADS 8
#define HD 16
#define HSUB 48
#define NKEY (HSUB*HSUB)

typedef unsigned long long u64;

// Scratch (device globals; no allocations allowed)
__device__ __align__(16) float g_q[NHEADS * NPIX * HD];   // [head][pix][16] (pre-scaled by 0.25)
__device__ __align__(16) float g_k[NHEADS * NKEY * HD];   // [head][48*48][16] (even rows/cols only)
__device__ __align__(16) float g_v[NHEADS * NKEY * HD];
__device__ __align__(16) float g_att[NPIX * 128];         // [pix][channel]

// ---- f32x2 packed math helpers -------------------------------------------
__device__ __forceinline__ u64 pk2(float lo, float hi) {
    u64 r; asm("mov.b64 %0,{%1,%2};" : "=l"(r) : "f"(lo), "f"(hi)); return r;
}
__device__ __forceinline__ void upk2(u64 p, float& lo, float& hi) {
    asm("mov.b64 {%0,%1},%2;" : "=f"(lo), "=f"(hi) : "l"(p));
}
__device__ __forceinline__ u64 ffma2(u64 a, u64 b, u64 c) {
    u64 d; asm("fma.rn.f32x2 %0,%1,%2,%3;" : "=l"(d) : "l"(a), "l"(b), "l"(c)); return d;
}
__device__ __forceinline__ u64 fmul2(u64 a, u64 b) {
    u64 d; asm("mul.rn.f32x2 %0,%1,%2;" : "=l"(d) : "l"(a), "l"(b)); return d;
}

// ---------------------------------------------------------------------------
// Kernel 1: grouped 3x3 conv, restructured by 16-channel output groups.
// Groups 0..7 = q (head = og), 8..15 = k (head = og-8), 16..23 = v (head = og-16).
// Group og consumes input channels ic0..ic0+5, ic0 = (16*og)/3.
// Grid: 96 q CTAs (12 row-tiles x 8 groups, 8 rows, 2 px/thread) +
//       96 kv CTAs (6 row-tiles x 16 groups, 16 rows, even pixels only).
// ---------------------------------------------------------------------------
#define HALO_Q 10
#define HALO_KV 18

template<int M>
__device__ __forceinline__ void conv_q_compute(const float* __restrict__ xs,
                                               const float* __restrict__ ws,
                                               const float* __restrict__ bs,
                                               int i0, int og, int tid) {
    const int r0 = tid / 96;
    const int j  = tid - r0 * 96;
    float accA[16], accB[16];
    #pragma unroll
    for (int icl = 0; icl < 6; icl++) {
        const float* p = xs + icl * (HALO_Q * 98) + (2 * r0) * 98 + j;
        const float v00 = p[0],   v01 = p[1],   v02 = p[2];
        const float v10 = p[98],  v11 = p[99],  v12 = p[100];
        const float v20 = p[196], v21 = p[197], v22 = p[198];
        const float v30 = p[294], v31 = p[295], v32 = p[296];
        #pragma unroll
        for (int r = 0; r < 3; r++) {
            const int c = icl * 3 + r - M;
            if (c >= 0 && c < 16) {
                const float* w = ws + c * 9;
                const float bb = bs[c];
                float a0 = bb, a1 = bb;
                a0 = fmaf(w[0], v00, a0); a0 = fmaf(w[1], v01, a0); a0 = fmaf(w[2], v02, a0);
                a0 = fmaf(w[3], v10, a0); a0 = fmaf(w[4], v11, a0); a0 = fmaf(w[5], v12, a0);
                a0 = fmaf(w[6], v20, a0); a0 = fmaf(w[7], v21, a0); a0 = fmaf(w[8], v22, a0);
                a1 = fmaf(w[0], v10, a1); a1 = fmaf(w[1], v11, a1); a1 = fmaf(w[2], v12, a1);
                a1 = fmaf(w[3], v20, a1); a1 = fmaf(w[4], v21, a1); a1 = fmaf(w[5], v22, a1);
                a1 = fmaf(w[6], v30, a1); a1 = fmaf(w[7], v31, a1); a1 = fmaf(w[8], v32, a1);
                accA[c] = a0 * 0.25f;
                accB[c] = a1 * 0.25f;
            }
        }
    }
    const int iA = i0 + 2 * r0;
    float4* gA = (float4*)(g_q + ((size_t)og * NPIX + (size_t)iA * 96 + j) * HD);
    float4* gB = (float4*)(g_q + ((size_t)og * NPIX + (size_t)(iA + 1) * 96 + j) * HD);
    #pragma unroll
    for (int e = 0; e < 4; e++) {
        gA[e] = make_float4(accA[4*e], accA[4*e+1], accA[4*e+2], accA[4*e+3]);
        gB[e] = make_float4(accB[4*e], accB[4*e+1], accB[4*e+2], accB[4*e+3]);
    }
}

template<int M>
__device__ __forceinline__ void conv_kv_compute(const float* __restrict__ xs,
                                                const float* __restrict__ ws,
                                                const float* __restrict__ bs,
                                                int i0, int og, int tid) {
    const int sr = tid / 48;         // 0..7 (even-row index within tile)
    const int sc = tid - sr * 48;    // 0..47 (even-col index)
    float acc[16];
    #pragma unroll
    for (int icl = 0; icl < 6; icl++) {
        const float* p = xs + icl * (HALO_KV * 98) + (2 * sr) * 98 + 2 * sc;
        const float v00 = p[0],   v01 = p[1],   v02 = p[2];
        const float v10 = p[98],  v11 = p[99],  v12 = p[100];
        const float v20 = p[196], v21 = p[197], v22 = p[198];
        #pragma unroll
        for (int r = 0; r < 3; r++) {
            const int c = icl * 3 + r - M;
            if (c >= 0 && c < 16) {
                const float* w = ws + c * 9;
                float a = bs[c];
                a = fmaf(w[0], v00, a); a = fmaf(w[1], v01, a); a = fmaf(w[2], v02, a);
                a = fmaf(w[3], v10, a); a = fmaf(w[4], v11, a); a = fmaf(w[5], v12, a);
                a = fmaf(w[6], v20, a); a = fmaf(w[7], v21, a); a = fmaf(w[8], v22, a);
                acc[c] = a;
            }
        }
    }
    float* dst = (og < 16) ? g_k : g_v;
    const int n = (og < 16) ? (og - 8) : (og - 16);
    const int kpix = (i0 / 2 + sr) * HSUB + sc;
    float4* gp = (float4*)(dst + ((size_t)n * NKEY + kpix) * HD);
    #pragma unroll
    for (int e = 0; e < 4; e++)
        gp[e] = make_float4(acc[4*e], acc[4*e+1], acc[4*e+2], acc[4*e+3]);
}

__global__ __launch_bounds__(384) void conv_qkv_kernel(
        const float* __restrict__ x,
        const float* __restrict__ wq,
        const float* __restrict__ bq) {
    __shared__ float xs[6 * HALO_KV * 98];
    __shared__ float ws[16 * 9];
    __shared__ float bs[16];
    const int bx = blockIdx.x;
    const int tid = threadIdx.x;

    const bool isq = bx < 96;
    int og, i0, H;
    if (isq) { og = bx & 7;             i0 = (bx >> 3) * 8;  H = HALO_Q;  }
    else     { int b = bx - 96;
               og = 8 + (b & 15);       i0 = (b >> 4) * 16;  H = HALO_KV; }
    const int o0 = og * 16;
    const int ic0 = o0 / 3;

    if (tid < 144) ws[tid] = wq[o0 * 9 + tid];
    if (tid < 16)  bs[tid] = bq[o0 + tid];

    // Load 6 channel tiles with row halo; zero-pad columns 0/97 and OOB rows.
    {
        const int tot = 6 * H * 96;
        const int hs = H * 96;
        for (int idx = tid; idx < tot; idx += 384) {
            int c = idx / hs;
            int rem = idx - c * hs;
            int r = rem / 96, col = rem - r * 96;
            int gi = i0 - 1 + r;
            float v = (gi >= 0 && gi < 96) ? x[(size_t)(ic0 + c) * NPIX + gi * 96 + col] : 0.f;
            xs[c * (H * 98) + r * 98 + col + 1] = v;
        }
        for (int idx = tid; idx < 6 * H; idx += 384) {
            xs[idx * 98] = 0.f;
            xs[idx * 98 + 97] = 0.f;
        }
    }
    __syncthreads();

    const int m = og % 3;   // (16*og) % 3 == og % 3
    if (isq) {
        if      (m == 0) conv_q_compute<0>(xs, ws, bs, i0, og, tid);
        else if (m == 1) conv_q_compute<1>(xs, ws, bs, i0, og, tid);
        else             conv_q_compute<2>(xs, ws, bs, i0, og, tid);
    } else {
        if      (m == 0) conv_kv_compute<0>(xs, ws, bs, i0, og, tid);
        else if (m == 1) conv_kv_compute<1>(xs, ws, bs, i0, og, tid);
        else             conv_kv_compute<2>(xs, ws, bs, i0, og, tid);
    }
}

// ---------------------------------------------------------------------------
// Kernel 2: neighborhood attention (f32x2 packed math).
// grid (6,6,8): CTA = (col-tile, row-tile, head), 16x16 queries per CTA,
// 16x16 key tile of the 48x48 subsampled grid in SMEM (stride 10 u64 = 80B
// per key -> conflict-free LDS.128).
// ---------------------------------------------------------------------------
__global__ __launch_bounds__(256) void attn_kernel() {
    __shared__ u64 Kt[256 * 10];
    __shared__ u64 Vt[256 * 10];
    const int tj = blockIdx.x, ti = blockIdx.y, n = blockIdx.z;
    const int tid = threadIdx.x;

    const int si0 = min(max(ti * 8 - 3, 0), 40);
    const int sj0 = min(max(tj * 8 - 3, 0), 40);

    {
        int kr = tid >> 4, kc = tid & 15;
        int gr = min(si0 + kr, 47);
        int gc = min(sj0 + kc, 47);
        const ulonglong2* kg = (const ulonglong2*)g_k + (size_t)(n * NKEY + gr * HSUB + gc) * 4;
        const ulonglong2* vg = (const ulonglong2*)g_v + (size_t)(n * NKEY + gr * HSUB + gc) * 4;
        #pragma unroll
        for (int e = 0; e < 4; e++) {
            ulonglong2 a = kg[e];
            Kt[tid * 10 + 2 * e]     = a.x;
            Kt[tid * 10 + 2 * e + 1] = a.y;
            ulonglong2 b = vg[e];
            Vt[tid * 10 + 2 * e]     = b.x;
            Vt[tid * 10 + 2 * e + 1] = b.y;
        }
    }
    __syncthreads();

    const int qil = tid >> 4, qjl = tid & 15;
    const int qi = ti * 16 + qil;
    const int qj = tj * 16 + qjl;
    const int reli = min(max((qi >> 1) - 3, 0), 40) - si0;
    const int relj = min(max((qj >> 1) - 3, 0), 40) - sj0;

    u64 qp[8];
    {
        // 16 floats per query = 4 x 16B vectors => index scale *4 (NOT *2)
        const ulonglong2* qg = (const ulonglong2*)g_q + (size_t)(n * NPIX + qi * 96 + qj) * 4;
        #pragma unroll
        for (int e = 0; e < 2; e++) {
            ulonglong2 a = qg[2 * e], b = qg[2 * e + 1];
            qp[4 * e] = a.x; qp[4 * e + 1] = a.y;
            qp[4 * e + 2] = b.x; qp[4 * e + 3] = b.y;
        }
    }

    float lg[64];
    float mx = -3.4e38f;
    #pragma unroll
    for (int p = 0; p < 8; p++) {
        const int rb = (reli + p) * 16 + relj;
        #pragma unroll
        for (int cc = 0; cc < 8; cc++) {
            const ulonglong2* kp = (const ulonglong2*)&Kt[(rb + cc) * 10];
            ulonglong2 k0 = kp[0], k1 = kp[1], k2 = kp[2], k3 = kp[3];
            u64 acc = fmul2(qp[0], k0.x);
            acc = ffma2(qp[1], k0.y, acc);
            acc = ffma2(qp[2], k1.x, acc);
            acc = ffma2(qp[3], k1.y, acc);
            acc = ffma2(qp[4], k2.x, acc);
            acc = ffma2(qp[5], k2.y, acc);
            acc = ffma2(qp[6], k3.x, acc);
            acc = ffma2(qp[7], k3.y, acc);
            float lo, hi; upk2(acc, lo, hi);
            float s = lo + hi;
            lg[p * 8 + cc] = s;
            mx = fmaxf(mx, s);
        }
    }

    float sum = 0.f;
    #pragma unroll
    for (int k = 0; k < 64; k++) {
        float e = __expf(lg[k] - mx);
        lg[k] = e;
        sum += e;
    }

    u64 av[8];
    #pragma unroll
    for (int e = 0; e < 8; e++) av[e] = 0ull;  // +0.0 packed

    #pragma unroll
    for (int p = 0; p < 8; p++) {
        const int rb = (reli + p) * 16 + relj;
        #pragma unroll
        for (int cc = 0; cc < 8; cc++) {
            const float wv = lg[p * 8 + cc];
            const u64 w2 = pk2(wv, wv);
            const ulonglong2* vp = (const ulonglong2*)&Vt[(rb + cc) * 10];
            ulonglong2 v0 = vp[0], v1 = vp[1], v2 = vp[2], v3 = vp[3];
            av[0] = ffma2(w2, v0.x, av[0]);
            av[1] = ffma2(w2, v0.y, av[1]);
            av[2] = ffma2(w2, v1.x, av[2]);
            av[3] = ffma2(w2, v1.y, av[3]);
            av[4] = ffma2(w2, v2.x, av[4]);
            av[5] = ffma2(w2, v2.y, av[5]);
            av[6] = ffma2(w2, v3.x, av[6]);
            av[7] = ffma2(w2, v3.y, av[7]);
        }
    }

    const float inv = 1.f / sum;
    const u64 inv2 = pk2(inv, inv);
    ulonglong2* og = (ulonglong2*)g_att + (size_t)(qi * 96 + qj) * 32 + n * 4;
    #pragma unroll
    for (int e = 0; e < 4; e++) {
        ulonglong2 o;
        o.x = fmul2(av[2 * e], inv2);
        o.y = fmul2(av[2 * e + 1], inv2);
        og[e] = o;
    }
}

// ---------------------------------------------------------------------------
// Kernel 3: 1x1 projection GEMM (f32x2 packed inner product).
// out[o][pix] = sum_c W[o][c]*att[pix][c] + b[o]
// CTA: 64 pixels x 128 outs, K=128 in two 64-chunks, thread tile 4 pix x 8 out.
// ---------------------------------------------------------------------------
__global__ __launch_bounds__(256) void proj_kernel(
        const float* __restrict__ pw,
        const float* __restrict__ pb,
        float* __restrict__ out) {
    __shared__ __align__(16) float As[64 * 64];    // [k][pix]
    __shared__ __align__(16) float Bs[64 * 128];   // [k][o]
    const int pix0 = blockIdx.x * 64;
    const int tid = threadIdx.x;
    const int tp = tid >> 4;       // pixel group 0..15
    const int tout = tid & 15;     // out group 0..15

    u64 acc2[4][4];
    #pragma unroll
    for (int pp = 0; pp < 4; pp++)
        #pragma unroll
        for (int q = 0; q < 4; q++) acc2[pp][q] = 0ull;

    for (int kt = 0; kt < 2; kt++) {
        __syncthreads();
        {
            int p = tid & 63, k4 = tid >> 6;   // k4 in 0..3
            const float4* src = (const float4*)g_att + (size_t)(pix0 + p) * 32 + kt * 16;
            #pragma unroll
            for (int r2 = 0; r2 < 4; r2++) {
                int kk = k4 + 4 * r2;          // 0..15
                float4 v = src[kk];
                As[(kk * 4 + 0) * 64 + p] = v.x;
                As[(kk * 4 + 1) * 64 + p] = v.y;
                As[(kk * 4 + 2) * 64 + p] = v.z;
                As[(kk * 4 + 3) * 64 + p] = v.w;
            }
        }
        {
            int o = tid & 127, g = tid >> 7;   // g in 0..1
            const float4* src = (const float4*)pw + (size_t)o * 32 + kt * 16;
            #pragma unroll
            for (int r2 = 0; r2 < 8; r2++) {
                int kk = g + 2 * r2;           // 0..15
                float4 v = src[kk];
                Bs[(kk * 4 + 0) * 128 + o] = v.x;
                Bs[(kk * 4 + 1) * 128 + o] = v.y;
                Bs[(kk * 4 + 2) * 128 + o] = v.z;
                Bs[(kk * 4 + 3) * 128 + o] = v.w;
            }
        }
        __syncthreads();

        #pragma unroll 8
        for (int k = 0; k < 64; k++) {
            float4 a = ((const float4*)As)[k * 16 + tp];
            ulonglong2 b0 = ((const ulonglong2*)Bs)[k * 32 + tout * 2];
            ulonglong2 b1 = ((const ulonglong2*)Bs)[k * 32 + tout * 2 + 1];
            u64 ap[4];
            ap[0] = pk2(a.x, a.x);
            ap[1] = pk2(a.y, a.y);
            ap[2] = pk2(a.z, a.z);
            ap[3] = pk2(a.w, a.w);
            #pragma unroll
            for (int pp = 0; pp < 4; pp++) {
                acc2[pp][0] = ffma2(ap[pp], b0.x, acc2[pp][0]);
                acc2[pp][1] = ffma2(ap[pp], b0.y, acc2[pp][1]);
                acc2[pp][2] = ffma2(ap[pp], b1.x, acc2[pp][2]);
                acc2[pp][3] = ffma2(ap[pp], b1.y, acc2[pp][3]);
            }
        }
    }

    float acc[4][8];
    #pragma unroll
    for (int pp = 0; pp < 4; pp++)
        #pragma unroll
        for (int q = 0; q < 4; q++)
            upk2(acc2[pp][q], acc[pp][2 * q], acc[pp][2 * q + 1]);

    #pragma unroll
    for (int oo = 0; oo < 8; oo++) {
        int o = tout * 8 + oo;
        float bias = pb[o];
        float4 r = make_float4(acc[0][oo] + bias, acc[1][oo] + bias,
                               acc[2][oo] + bias, acc[3][oo] + bias);
        *(float4*)(out + (size_t)o * NPIX + pix0 + tp * 4) = r;
    }
}

// ---------------------------------------------------------------------------
extern "C" void kernel_launch(void* const* d_in, const int* in_sizes, int n_in,
                              void* d_out, int out_size) {
    const float* x      = (const float*)d_in[0];
    const float* qkv_w  = (const float*)d_in[1];
    const float* qkv_b  = (const float*)d_in[2];
    const float* proj_w = (const float*)d_in[3];
    const float* proj_b = (const float*)d_in[4];
    float* out = (float*)d_out;

    conv_qkv_kernel<<<192, 384>>>(x, qkv_w, qkv_b);
    attn_kernel<<<dim3(6, 6, NHEADS), 256>>>();
    proj_kernel<<<144, 256>>>(proj_w, proj_b, out);
}

// round 5
// speedup vs baseline: 1.2059x; 1.0548x over previous
#include <cuda_runtime.h>

#define HH 96
#define WW 96
#define NPIX 9216
#define NHEADS 8
#define HD 16
#define HSUB 48
#define NKEY (HSUB*HSUB)

typedef unsigned long long u64;

// Scratch (device globals; no allocations allowed)
__device__ __align__(16) float g_q[NHEADS * NPIX * HD];   // [head][pix][16] (pre-scaled by 0.25)
__device__ __align__(16) float g_k[NHEADS * NKEY * HD];   // [head][48*48][16] (even rows/cols only)
__device__ __align__(16) float g_v[NHEADS * NKEY * HD];
__device__ __align__(16) float g_att[NPIX * 128];         // [pix][channel]

// ---- f32x2 packed math helpers -------------------------------------------
__device__ __forceinline__ u64 pk2(float lo, float hi) {
    u64 r; asm("mov.b64 %0,{%1,%2};" : "=l"(r) : "f"(lo), "f"(hi)); return r;
}
__device__ __forceinline__ void upk2(u64 p, float& lo, float& hi) {
    asm("mov.b64 {%0,%1},%2;" : "=f"(lo), "=f"(hi) : "l"(p));
}
__device__ __forceinline__ u64 ffma2(u64 a, u64 b, u64 c) {
    u64 d; asm("fma.rn.f32x2 %0,%1,%2,%3;" : "=l"(d) : "l"(a), "l"(b), "l"(c)); return d;
}
__device__ __forceinline__ u64 fmul2(u64 a, u64 b) {
    u64 d; asm("mul.rn.f32x2 %0,%1,%2;" : "=l"(d) : "l"(a), "l"(b)); return d;
}

// ---------------------------------------------------------------------------
// Kernel 1: grouped 3x3 conv by 16-channel output groups, small tiles.
// Groups 0..7 = q (head = og), 8..15 = k, 16..23 = v.
// q CTAs: 192 = 8 groups x 24 tiles of 4 rows (halo 6).  1 px/thread.
// kv CTAs: 192 = 16 groups x 12 tiles of 4 sub-rows (halo 9). even px only.
// ---------------------------------------------------------------------------
#define HALO_Q 6
#define HALO_KV 9

template<int M>
__device__ __forceinline__ void conv_q_compute(const float* __restrict__ xs,
                                               const float* __restrict__ ws,
                                               const float* __restrict__ bs,
                                               int i0, int og, int tid) {
    const int r0 = tid / 96;          // 0..3
    const int j  = tid - r0 * 96;     // 0..95
    float acc[16];
    #pragma unroll
    for (int icl = 0; icl < 6; icl++) {
        const float* p = xs + icl * (HALO_Q * 98) + r0 * 98 + j;
        const float v00 = p[0],   v01 = p[1],   v02 = p[2];
        const float v10 = p[98],  v11 = p[99],  v12 = p[100];
        const float v20 = p[196], v21 = p[197], v22 = p[198];
        #pragma unroll
        for (int r = 0; r < 3; r++) {
            const int c = icl * 3 + r - M;
            if (c >= 0 && c < 16) {
                const float* w = ws + c * 9;
                float a = bs[c];
                a = fmaf(w[0], v00, a); a = fmaf(w[1], v01, a); a = fmaf(w[2], v02, a);
                a = fmaf(w[3], v10, a); a = fmaf(w[4], v11, a); a = fmaf(w[5], v12, a);
                a = fmaf(w[6], v20, a); a = fmaf(w[7], v21, a); a = fmaf(w[8], v22, a);
                acc[c] = a * 0.25f;
            }
        }
    }
    const int i = i0 + r0;
    float4* gp = (float4*)(g_q + ((size_t)og * NPIX + (size_t)i * 96 + j) * HD);
    #pragma unroll
    for (int e = 0; e < 4; e++)
        gp[e] = make_float4(acc[4*e], acc[4*e+1], acc[4*e+2], acc[4*e+3]);
}

template<int M>
__device__ __forceinline__ void conv_kv_compute(const float* __restrict__ xs,
                                                const float* __restrict__ ws,
                                                const float* __restrict__ bs,
                                                int sr0, int og, int tid) {
    if (tid >= 192) return;
    const int sr = tid / 48;          // 0..3 local sub-row
    const int sc = tid - sr * 48;     // 0..47
    float acc[16];
    #pragma unroll
    for (int icl = 0; icl < 6; icl++) {
        const float* p = xs + icl * (HALO_KV * 98) + (2 * sr) * 98 + 2 * sc;
        const float v00 = p[0],   v01 = p[1],   v02 = p[2];
        const float v10 = p[98],  v11 = p[99],  v12 = p[100];
        const float v20 = p[196], v21 = p[197], v22 = p[198];
        #pragma unroll
        for (int r = 0; r < 3; r++) {
            const int c = icl * 3 + r - M;
            if (c >= 0 && c < 16) {
                const float* w = ws + c * 9;
                float a = bs[c];
                a = fmaf(w[0], v00, a); a = fmaf(w[1], v01, a); a = fmaf(w[2], v02, a);
                a = fmaf(w[3], v10, a); a = fmaf(w[4], v11, a); a = fmaf(w[5], v12, a);
                a = fmaf(w[6], v20, a); a = fmaf(w[7], v21, a); a = fmaf(w[8], v22, a);
                acc[c] = a;
            }
        }
    }
    float* dst = (og < 16) ? g_k : g_v;
    const int n = (og < 16) ? (og - 8) : (og - 16);
    const int kpix = (sr0 + sr) * HSUB + sc;
    float4* gp = (float4*)(dst + ((size_t)n * NKEY + kpix) * HD);
    #pragma unroll
    for (int e = 0; e < 4; e++)
        gp[e] = make_float4(acc[4*e], acc[4*e+1], acc[4*e+2], acc[4*e+3]);
}

__global__ __launch_bounds__(384, 2) void conv_qkv_kernel(
        const float* __restrict__ x,
        const float* __restrict__ wq,
        const float* __restrict__ bq) {
    __shared__ float xs[6 * HALO_KV * 98];
    __shared__ float ws[16 * 9];
    __shared__ float bs[16];
    const int bx = blockIdx.x;
    const int tid = threadIdx.x;

    const bool isq = bx < 192;
    int og, i0, H, sr0 = 0;
    if (isq) { og = bx & 7;            i0 = (bx >> 3) * 4;   H = HALO_Q;  }
    else     { int b = bx - 192;
               og = 8 + (b & 15);      sr0 = (b >> 4) * 4;
               i0 = sr0 * 2;           H = HALO_KV; }
    const int o0 = og * 16;
    const int ic0 = o0 / 3;

    if (tid < 144) ws[tid] = wq[o0 * 9 + tid];
    if (tid < 16)  bs[tid] = bq[o0 + tid];

    // Stage 6 channel tiles (H rows each, float4 global loads);
    // zero-pad columns 0/97 and OOB rows.
    {
        const int tot4 = 6 * H * 24;       // float4 count
        for (int idx = tid; idx < tot4; idx += 384) {
            int rall = idx / 24, col4 = idx - rall * 24;
            int c = rall / H, r = rall - c * H;
            int gi = i0 - 1 + r;
            float4 v = make_float4(0.f, 0.f, 0.f, 0.f);
            if (gi >= 0 && gi < 96)
                v = *(const float4*)(x + (size_t)(ic0 + c) * NPIX + gi * 96 + col4 * 4);
            float* d = &xs[(c * H + r) * 98 + 1 + col4 * 4];
            d[0] = v.x; d[1] = v.y; d[2] = v.z; d[3] = v.w;
        }
        for (int idx = tid; idx < 6 * H; idx += 384) {
            xs[idx * 98] = 0.f;
            xs[idx * 98 + 97] = 0.f;
        }
    }
    __syncthreads();

    const int m = og % 3;   // (16*og) % 3 == og % 3
    if (isq) {
        if      (m == 0) conv_q_compute<0>(xs, ws, bs, i0, og, tid);
        else if (m == 1) conv_q_compute<1>(xs, ws, bs, i0, og, tid);
        else             conv_q_compute<2>(xs, ws, bs, i0, og, tid);
    } else {
        if      (m == 0) conv_kv_compute<0>(xs, ws, bs, sr0, og, tid);
        else if (m == 1) conv_kv_compute<1>(xs, ws, bs, sr0, og, tid);
        else             conv_kv_compute<2>(xs, ws, bs, sr0, og, tid);
    }
}

// ---------------------------------------------------------------------------
// Kernel 2: neighborhood attention, flash-style 2-chunk softmax (32 keys per
// chunk) to cut live registers -> 2 CTAs/SM via __launch_bounds__(256,2).
// grid (6,6,8): CTA = (col-tile, row-tile, head), 16x16 queries, 16x16 key
// tile in SMEM (80B stride -> conflict-free LDS.128; within a warp the 4
// lanes of each 2x2 query block broadcast-read the same key address).
// ---------------------------------------------------------------------------
__global__ __launch_bounds__(256, 2) void attn_kernel() {
    __shared__ u64 Kt[256 * 10];
    __shared__ u64 Vt[256 * 10];
    const int tj = blockIdx.x, ti = blockIdx.y, n = blockIdx.z;
    const int tid = threadIdx.x;

    const int si0 = min(max(ti * 8 - 3, 0), 40);
    const int sj0 = min(max(tj * 8 - 3, 0), 40);

    {
        int kr = tid >> 4, kc = tid & 15;
        int gr = min(si0 + kr, 47);
        int gc = min(sj0 + kc, 47);
        const ulonglong2* kg = (const ulonglong2*)g_k + (size_t)(n * NKEY + gr * HSUB + gc) * 4;
        const ulonglong2* vg = (const ulonglong2*)g_v + (size_t)(n * NKEY + gr * HSUB + gc) * 4;
        #pragma unroll
        for (int e = 0; e < 4; e++) {
            ulonglong2 a = kg[e];
            Kt[tid * 10 + 2 * e]     = a.x;
            Kt[tid * 10 + 2 * e + 1] = a.y;
            ulonglong2 b = vg[e];
            Vt[tid * 10 + 2 * e]     = b.x;
            Vt[tid * 10 + 2 * e + 1] = b.y;
        }
    }
    __syncthreads();

    const int qil = tid >> 4, qjl = tid & 15;
    const int qi = ti * 16 + qil;
    const int qj = tj * 16 + qjl;
    const int reli = min(max((qi >> 1) - 3, 0), 40) - si0;
    const int relj = min(max((qj >> 1) - 3, 0), 40) - sj0;

    u64 qp[8];
    {
        const ulonglong2* qg = (const ulonglong2*)g_q + (size_t)(n * NPIX + qi * 96 + qj) * 4;
        #pragma unroll
        for (int e = 0; e < 2; e++) {
            ulonglong2 a = qg[2 * e], b = qg[2 * e + 1];
            qp[4 * e] = a.x; qp[4 * e + 1] = a.y;
            qp[4 * e + 2] = b.x; qp[4 * e + 3] = b.y;
        }
    }

    float mx = -3.4e38f;
    float sum = 0.f;
    u64 av[8];
    #pragma unroll
    for (int e = 0; e < 8; e++) av[e] = 0ull;

    #pragma unroll
    for (int ch = 0; ch < 2; ch++) {
        float lg[32];
        float cmx = -3.4e38f;
        #pragma unroll
        for (int p = 0; p < 4; p++) {
            const int rb = (reli + ch * 4 + p) * 16 + relj;
            #pragma unroll
            for (int cc = 0; cc < 8; cc++) {
                const ulonglong2* kp = (const ulonglong2*)&Kt[(rb + cc) * 10];
                ulonglong2 k0 = kp[0], k1 = kp[1], k2 = kp[2], k3 = kp[3];
                u64 acc = fmul2(qp[0], k0.x);
                acc = ffma2(qp[1], k0.y, acc);
                acc = ffma2(qp[2], k1.x, acc);
                acc = ffma2(qp[3], k1.y, acc);
                acc = ffma2(qp[4], k2.x, acc);
                acc = ffma2(qp[5], k2.y, acc);
                acc = ffma2(qp[6], k3.x, acc);
                acc = ffma2(qp[7], k3.y, acc);
                float lo, hi; upk2(acc, lo, hi);
                float s = lo + hi;
                lg[p * 8 + cc] = s;
                cmx = fmaxf(cmx, s);
            }
        }
        const float nmx = fmaxf(mx, cmx);
        const float resc = __expf(mx - nmx);   // 0 on first chunk
        sum *= resc;
        const u64 resc2 = pk2(resc, resc);
        #pragma unroll
        for (int e = 0; e < 8; e++) av[e] = fmul2(av[e], resc2);
        mx = nmx;

        #pragma unroll
        for (int k = 0; k < 32; k++) {
            float e = __expf(lg[k] - nmx);
            lg[k] = e;
            sum += e;
        }

        #pragma unroll
        for (int p = 0; p < 4; p++) {
            const int rb = (reli + ch * 4 + p) * 16 + relj;
            #pragma unroll
            for (int cc = 0; cc < 8; cc++) {
                const float wv = lg[p * 8 + cc];
                const u64 w2 = pk2(wv, wv);
                const ulonglong2* vp = (const ulonglong2*)&Vt[(rb + cc) * 10];
                ulonglong2 v0 = vp[0], v1 = vp[1], v2 = vp[2], v3 = vp[3];
                av[0] = ffma2(w2, v0.x, av[0]);
                av[1] = ffma2(w2, v0.y, av[1]);
                av[2] = ffma2(w2, v1.x, av[2]);
                av[3] = ffma2(w2, v1.y, av[3]);
                av[4] = ffma2(w2, v2.x, av[4]);
                av[5] = ffma2(w2, v2.y, av[5]);
                av[6] = ffma2(w2, v3.x, av[6]);
                av[7] = ffma2(w2, v3.y, av[7]);
            }
        }
    }

    const float inv = 1.f / sum;
    const u64 inv2 = pk2(inv, inv);
    ulonglong2* og = (ulonglong2*)g_att + (size_t)(qi * 96 + qj) * 32 + n * 4;
    #pragma unroll
    for (int e = 0; e < 4; e++) {
        ulonglong2 o;
        o.x = fmul2(av[2 * e], inv2);
        o.y = fmul2(av[2 * e + 1], inv2);
        og[e] = o;
    }
}

// ---------------------------------------------------------------------------
// Kernel 3: 1x1 projection GEMM (f32x2 packed inner product).
// out[o][pix] = sum_c W[o][c]*att[pix][c] + b[o]
// CTA: 64 pixels x 128 outs, K=128 in two 64-chunks, thread tile 4 pix x 8 out.
// ---------------------------------------------------------------------------
__global__ __launch_bounds__(256) void proj_kernel(
        const float* __restrict__ pw,
        const float* __restrict__ pb,
        float* __restrict__ out) {
    __shared__ __align__(16) float As[64 * 64];    // [k][pix]
    __shared__ __align__(16) float Bs[64 * 128];   // [k][o]
    const int pix0 = blockIdx.x * 64;
    const int tid = threadIdx.x;
    const int tp = tid >> 4;       // pixel group 0..15
    const int tout = tid & 15;     // out group 0..15

    u64 acc2[4][4];
    #pragma unroll
    for (int pp = 0; pp < 4; pp++)
        #pragma unroll
        for (int q = 0; q < 4; q++) acc2[pp][q] = 0ull;

    for (int kt = 0; kt < 2; kt++) {
        __syncthreads();
        {
            int p = tid & 63, k4 = tid >> 6;   // k4 in 0..3
            const float4* src = (const float4*)g_att + (size_t)(pix0 + p) * 32 + kt * 16;
            #pragma unroll
            for (int r2 = 0; r2 < 4; r2++) {
                int kk = k4 + 4 * r2;          // 0..15
                float4 v = src[kk];
                As[(kk * 4 + 0) * 64 + p] = v.x;
                As[(kk * 4 + 1) * 64 + p] = v.y;
                As[(kk * 4 + 2) * 64 + p] = v.z;
                As[(kk * 4 + 3) * 64 + p] = v.w;
            }
        }
        {
            int o = tid & 127, g = tid >> 7;   // g in 0..1
            const float4* src = (const float4*)pw + (size_t)o * 32 + kt * 16;
            #pragma unroll
            for (int r2 = 0; r2 < 8; r2++) {
                int kk = g + 2 * r2;           // 0..15
                float4 v = src[kk];
                Bs[(kk * 4 + 0) * 128 + o] = v.x;
                Bs[(kk * 4 + 1) * 128 + o] = v.y;
                Bs[(kk * 4 + 2) * 128 + o] = v.z;
                Bs[(kk * 4 + 3) * 128 + o] = v.w;
            }
        }
        __syncthreads();

        #pragma unroll 8
        for (int k = 0; k < 64; k++) {
            float4 a = ((const float4*)As)[k * 16 + tp];
            ulonglong2 b0 = ((const ulonglong2*)Bs)[k * 32 + tout * 2];
            ulonglong2 b1 = ((const ulonglong2*)Bs)[k * 32 + tout * 2 + 1];
            u64 ap[4];
            ap[0] = pk2(a.x, a.x);
            ap[1] = pk2(a.y, a.y);
            ap[2] = pk2(a.z, a.z);
            ap[3] = pk2(a.w, a.w);
            #pragma unroll
            for (int pp = 0; pp < 4; pp++) {
                acc2[pp][0] = ffma2(ap[pp], b0.x, acc2[pp][0]);
                acc2[pp][1] = ffma2(ap[pp], b0.y, acc2[pp][1]);
                acc2[pp][2] = ffma2(ap[pp], b1.x, acc2[pp][2]);
                acc2[pp][3] = ffma2(ap[pp], b1.y, acc2[pp][3]);
            }
        }
    }

    float acc[4][8];
    #pragma unroll
    for (int pp = 0; pp < 4; pp++)
        #pragma unroll
        for (int q = 0; q < 4; q++)
            upk2(acc2[pp][q], acc[pp][2 * q], acc[pp][2 * q + 1]);

    #pragma unroll
    for (int oo = 0; oo < 8; oo++) {
        int o = tout * 8 + oo;
        float bias = pb[o];
        float4 r = make_float4(acc[0][oo] + bias, acc[1][oo] + bias,
                               acc[2][oo] + bias, acc[3][oo] + bias);
        *(float4*)(out + (size_t)o * NPIX + pix0 + tp * 4) = r;
    }
}

// ---------------------------------------------------------------------------
extern "C" void kernel_launch(void* const* d_in, const int* in_sizes, int n_in,
                              void* d_out, int out_size) {
    const float* x      = (const float*)d_in[0];
    const float* qkv_w  = (const float*)d_in[1];
    const float* qkv_b  = (const float*)d_in[2];
    const float* proj_w = (const float*)d_in[3];
    const float* proj_b = (const float*)d_in[4];
    float* out = (float*)d_out;

    conv_qkv_kernel<<<384, 384>>>(x, qkv_w, qkv_b);
    attn_kernel<<<dim3(6, 6, NHEADS), 256>>>();
    proj_kernel<<<144, 256>>>(proj_w, proj_b, out);
}

// round 6
// speedup vs baseline: 1.3279x; 1.1011x over previous
#include <cuda_runtime.h>

#define HH 96
#define WW 96
#define NPIX 9216
#define NHEADS 8
#define HD 16
#define HSUB 48
#define NKEY (HSUB*HSUB)

typedef unsigned long long u64;

// Planar scratch layouts (coalesced: plane-major, pixel-minor).
// q:   plane = head*4+e (e = d/4), offset = pixel (96x96)
// k/v: plane = head*4+e, offset = key (48x48 subsampled grid)
// att: plane = channel/4 (32 planes), offset = pixel
__device__ __align__(16) float4 g_q4[NHEADS * 4 * NPIX];
__device__ __align__(16) float4 g_k4[NHEADS * 4 * NKEY];
__device__ __align__(16) float4 g_v4[NHEADS * 4 * NKEY];
__device__ __align__(16) float4 g_att4[32 * NPIX];

// ---- f32x2 packed math helpers -------------------------------------------
__device__ __forceinline__ u64 pk2(float lo, float hi) {
    u64 r; asm("mov.b64 %0,{%1,%2};" : "=l"(r) : "f"(lo), "f"(hi)); return r;
}
__device__ __forceinline__ void upk2(u64 p, float& lo, float& hi) {
    asm("mov.b64 {%0,%1},%2;" : "=f"(lo), "=f"(hi) : "l"(p));
}
__device__ __forceinline__ u64 ffma2(u64 a, u64 b, u64 c) {
    u64 d; asm("fma.rn.f32x2 %0,%1,%2,%3;" : "=l"(d) : "l"(a), "l"(b), "l"(c)); return d;
}
__device__ __forceinline__ u64 fmul2(u64 a, u64 b) {
    u64 d; asm("mul.rn.f32x2 %0,%1,%2;" : "=l"(d) : "l"(a), "l"(b)); return d;
}

// ---------------------------------------------------------------------------
// Kernel 1: grouped 3x3 conv by 16-channel output groups, small tiles.
// Groups 0..7 = q (head = og), 8..15 = k, 16..23 = v.
// q CTAs: 192 = 8 groups x 24 tiles of 4 rows (halo 6).  1 px/thread.
// kv CTAs: 192 = 16 groups x 12 tiles of 4 sub-rows (halo 9). even px only.
// All global stores are planar float4 -> fully coalesced.
// ---------------------------------------------------------------------------
#define HALO_Q 6
#define HALO_KV 9

template<int M>
__device__ __forceinline__ void conv_q_compute(const float* __restrict__ xs,
                                               const float* __restrict__ ws,
                                               const float* __restrict__ bs,
                                               int i0, int og, int tid) {
    const int r0 = tid / 96;          // 0..3
    const int j  = tid - r0 * 96;     // 0..95
    float acc[16];
    #pragma unroll
    for (int icl = 0; icl < 6; icl++) {
        const float* p = xs + icl * (HALO_Q * 98) + r0 * 98 + j;
        const float v00 = p[0],   v01 = p[1],   v02 = p[2];
        const float v10 = p[98],  v11 = p[99],  v12 = p[100];
        const float v20 = p[196], v21 = p[197], v22 = p[198];
        #pragma unroll
        for (int r = 0; r < 3; r++) {
            const int c = icl * 3 + r - M;
            if (c >= 0 && c < 16) {
                const float* w = ws + c * 9;
                float a = bs[c];
                a = fmaf(w[0], v00, a); a = fmaf(w[1], v01, a); a = fmaf(w[2], v02, a);
                a = fmaf(w[3], v10, a); a = fmaf(w[4], v11, a); a = fmaf(w[5], v12, a);
                a = fmaf(w[6], v20, a); a = fmaf(w[7], v21, a); a = fmaf(w[8], v22, a);
                acc[c] = a * 0.25f;
            }
        }
    }
    const int pix = (i0 + r0) * 96 + j;
    float4* gp = g_q4 + (size_t)(og * 4) * NPIX + pix;
    #pragma unroll
    for (int e = 0; e < 4; e++)
        gp[e * NPIX] = make_float4(acc[4*e], acc[4*e+1], acc[4*e+2], acc[4*e+3]);
}

template<int M>
__device__ __forceinline__ void conv_kv_compute(const float* __restrict__ xs,
                                                const float* __restrict__ ws,
                                                const float* __restrict__ bs,
                                                int sr0, int og, int tid) {
    if (tid >= 192) return;
    const int sr = tid / 48;          // 0..3 local sub-row
    const int sc = tid - sr * 48;     // 0..47
    float acc[16];
    #pragma unroll
    for (int icl = 0; icl < 6; icl++) {
        const float* p = xs + icl * (HALO_KV * 98) + (2 * sr) * 98 + 2 * sc;
        const float v00 = p[0],   v01 = p[1],   v02 = p[2];
        const float v10 = p[98],  v11 = p[99],  v12 = p[100];
        const float v20 = p[196], v21 = p[197], v22 = p[198];
        #pragma unroll
        for (int r = 0; r < 3; r++) {
            const int c = icl * 3 + r - M;
            if (c >= 0 && c < 16) {
                const float* w = ws + c * 9;
                float a = bs[c];
                a = fmaf(w[0], v00, a); a = fmaf(w[1], v01, a); a = fmaf(w[2], v02, a);
                a = fmaf(w[3], v10, a); a = fmaf(w[4], v11, a); a = fmaf(w[5], v12, a);
                a = fmaf(w[6], v20, a); a = fmaf(w[7], v21, a); a = fmaf(w[8], v22, a);
                acc[c] = a;
            }
        }
    }
    float4* dst = (og < 16) ? g_k4 : g_v4;
    const int n = (og < 16) ? (og - 8) : (og - 16);
    const int kpix = (sr0 + sr) * HSUB + sc;
    float4* gp = dst + (size_t)(n * 4) * NKEY + kpix;
    #pragma unroll
    for (int e = 0; e < 4; e++)
        gp[e * NKEY] = make_float4(acc[4*e], acc[4*e+1], acc[4*e+2], acc[4*e+3]);
}

__global__ __launch_bounds__(384, 2) void conv_qkv_kernel(
        const float* __restrict__ x,
        const float* __restrict__ wq,
        const float* __restrict__ bq) {
    __shared__ float xs[6 * HALO_KV * 98];
    __shared__ float ws[16 * 9];
    __shared__ float bs[16];
    const int bx = blockIdx.x;
    const int tid = threadIdx.x;

    const bool isq = bx < 192;
    int og, i0, H, sr0 = 0;
    if (isq) { og = bx & 7;            i0 = (bx >> 3) * 4;   H = HALO_Q;  }
    else     { int b = bx - 192;
               og = 8 + (b & 15);      sr0 = (b >> 4) * 4;
               i0 = sr0 * 2;           H = HALO_KV; }
    const int o0 = og * 16;
    const int ic0 = o0 / 3;

    if (tid < 144) ws[tid] = wq[o0 * 9 + tid];
    if (tid < 16)  bs[tid] = bq[o0 + tid];

    // Stage 6 channel tiles (H rows each, float4 global loads);
    // zero-pad columns 0/97 and OOB rows.
    {
        const int tot4 = 6 * H * 24;       // float4 count
        for (int idx = tid; idx < tot4; idx += 384) {
            int rall = idx / 24, col4 = idx - rall * 24;
            int c = rall / H, r = rall - c * H;
            int gi = i0 - 1 + r;
            float4 v = make_float4(0.f, 0.f, 0.f, 0.f);
            if (gi >= 0 && gi < 96)
                v = *(const float4*)(x + (size_t)(ic0 + c) * NPIX + gi * 96 + col4 * 4);
            float* d = &xs[(c * H + r) * 98 + 1 + col4 * 4];
            d[0] = v.x; d[1] = v.y; d[2] = v.z; d[3] = v.w;
        }
        for (int idx = tid; idx < 6 * H; idx += 384) {
            xs[idx * 98] = 0.f;
            xs[idx * 98 + 97] = 0.f;
        }
    }
    __syncthreads();

    const int m = og % 3;   // (16*og) % 3 == og % 3
    if (isq) {
        if      (m == 0) conv_q_compute<0>(xs, ws, bs, i0, og, tid);
        else if (m == 1) conv_q_compute<1>(xs, ws, bs, i0, og, tid);
        else             conv_q_compute<2>(xs, ws, bs, i0, og, tid);
    } else {
        if      (m == 0) conv_kv_compute<0>(xs, ws, bs, sr0, og, tid);
        else if (m == 1) conv_kv_compute<1>(xs, ws, bs, sr0, og, tid);
        else             conv_kv_compute<2>(xs, ws, bs, sr0, og, tid);
    }
}

// ---------------------------------------------------------------------------
// Kernel 2: neighborhood attention, flash-style 2-chunk softmax, planar
// coalesced global loads/stores, 80B-stride SMEM tiles (conflict-free).
// grid (6,6,8): CTA = (col-tile, row-tile, head), 16x16 queries.
// ---------------------------------------------------------------------------
__global__ __launch_bounds__(256, 2) void attn_kernel() {
    __shared__ u64 Kt[256 * 10];
    __shared__ u64 Vt[256 * 10];
    const int tj = blockIdx.x, ti = blockIdx.y, n = blockIdx.z;
    const int tid = threadIdx.x;

    const int si0 = min(max(ti * 8 - 3, 0), 40);
    const int sj0 = min(max(tj * 8 - 3, 0), 40);

    {
        int kr = tid >> 4, kc = tid & 15;
        int gr = min(si0 + kr, 47);
        int gc = min(sj0 + kc, 47);
        const int key = gr * HSUB + gc;
        const ulonglong2* kg = (const ulonglong2*)g_k4 + (size_t)(n * 4) * NKEY + key;
        const ulonglong2* vg = (const ulonglong2*)g_v4 + (size_t)(n * 4) * NKEY + key;
        #pragma unroll
        for (int e = 0; e < 4; e++) {
            ulonglong2 a = kg[e * NKEY];
            Kt[tid * 10 + 2 * e]     = a.x;
            Kt[tid * 10 + 2 * e + 1] = a.y;
            ulonglong2 b = vg[e * NKEY];
            Vt[tid * 10 + 2 * e]     = b.x;
            Vt[tid * 10 + 2 * e + 1] = b.y;
        }
    }
    __syncthreads();

    const int qil = tid >> 4, qjl = tid & 15;
    const int qi = ti * 16 + qil;
    const int qj = tj * 16 + qjl;
    const int pix = qi * 96 + qj;
    const int reli = min(max((qi >> 1) - 3, 0), 40) - si0;
    const int relj = min(max((qj >> 1) - 3, 0), 40) - sj0;

    u64 qp[8];
    {
        const ulonglong2* qg = (const ulonglong2*)g_q4 + (size_t)(n * 4) * NPIX + pix;
        #pragma unroll
        for (int e = 0; e < 4; e++) {
            ulonglong2 a = qg[e * NPIX];
            qp[2 * e] = a.x; qp[2 * e + 1] = a.y;
        }
    }

    float mx = -3.4e38f;
    float sum = 0.f;
    u64 av[8];
    #pragma unroll
    for (int e = 0; e < 8; e++) av[e] = 0ull;

    #pragma unroll
    for (int ch = 0; ch < 2; ch++) {
        float lg[32];
        float cmx = -3.4e38f;
        #pragma unroll
        for (int p = 0; p < 4; p++) {
            const int rb = (reli + ch * 4 + p) * 16 + relj;
            #pragma unroll
            for (int cc = 0; cc < 8; cc++) {
                const ulonglong2* kp = (const ulonglong2*)&Kt[(rb + cc) * 10];
                ulonglong2 k0 = kp[0], k1 = kp[1], k2 = kp[2], k3 = kp[3];
                u64 acc = fmul2(qp[0], k0.x);
                acc = ffma2(qp[1], k0.y, acc);
                acc = ffma2(qp[2], k1.x, acc);
                acc = ffma2(qp[3], k1.y, acc);
                acc = ffma2(qp[4], k2.x, acc);
                acc = ffma2(qp[5], k2.y, acc);
                acc = ffma2(qp[6], k3.x, acc);
                acc = ffma2(qp[7], k3.y, acc);
                float lo, hi; upk2(acc, lo, hi);
                float s = lo + hi;
                lg[p * 8 + cc] = s;
                cmx = fmaxf(cmx, s);
            }
        }
        const float nmx = fmaxf(mx, cmx);
        const float resc = __expf(mx - nmx);   // 0 on first chunk
        sum *= resc;
        const u64 resc2 = pk2(resc, resc);
        #pragma unroll
        for (int e = 0; e < 8; e++) av[e] = fmul2(av[e], resc2);
        mx = nmx;

        #pragma unroll
        for (int k = 0; k < 32; k++) {
            float e = __expf(lg[k] - nmx);
            lg[k] = e;
            sum += e;
        }

        #pragma unroll
        for (int p = 0; p < 4; p++) {
            const int rb = (reli + ch * 4 + p) * 16 + relj;
            #pragma unroll
            for (int cc = 0; cc < 8; cc++) {
                const float wv = lg[p * 8 + cc];
                const u64 w2 = pk2(wv, wv);
                const ulonglong2* vp = (const ulonglong2*)&Vt[(rb + cc) * 10];
                ulonglong2 v0 = vp[0], v1 = vp[1], v2 = vp[2], v3 = vp[3];
                av[0] = ffma2(w2, v0.x, av[0]);
                av[1] = ffma2(w2, v0.y, av[1]);
                av[2] = ffma2(w2, v1.x, av[2]);
                av[3] = ffma2(w2, v1.y, av[3]);
                av[4] = ffma2(w2, v2.x, av[4]);
                av[5] = ffma2(w2, v2.y, av[5]);
                av[6] = ffma2(w2, v3.x, av[6]);
                av[7] = ffma2(w2, v3.y, av[7]);
            }
        }
    }

    const float inv = 1.f / sum;
    const u64 inv2 = pk2(inv, inv);
    ulonglong2* og = (ulonglong2*)g_att4 + (size_t)(n * 4) * NPIX + pix;
    #pragma unroll
    for (int e = 0; e < 4; e++) {
        ulonglong2 o;
        o.x = fmul2(av[2 * e], inv2);
        o.y = fmul2(av[2 * e + 1], inv2);
        og[e * NPIX] = o;
    }
}

// ---------------------------------------------------------------------------
// Kernel 3: 1x1 projection GEMM (f32x2 packed inner product).
// out[o][pix] = sum_c W[o][c]*att[pix][c] + b[o]
// g_att4 planar: channel c lives in plane c>>2, lane c&3 -> coalesced loads.
// CTA: 64 pixels x 128 outs, K=128 in two 64-chunks, thread tile 4 pix x 8 out.
// ---------------------------------------------------------------------------
__global__ __launch_bounds__(256) void proj_kernel(
        const float* __restrict__ pw,
        const float* __restrict__ pb,
        float* __restrict__ out) {
    __shared__ __align__(16) float As[64 * 64];    // [k][pix]
    __shared__ __align__(16) float Bs[64 * 128];   // [k][o]
    const int pix0 = blockIdx.x * 64;
    const int tid = threadIdx.x;
    const int tp = tid >> 4;       // pixel group 0..15
    const int tout = tid & 15;     // out group 0..15

    u64 acc2[4][4];
    #pragma unroll
    for (int pp = 0; pp < 4; pp++)
        #pragma unroll
        for (int q = 0; q < 4; q++) acc2[pp][q] = 0ull;

    for (int kt = 0; kt < 2; kt++) {
        __syncthreads();
        {
            int p = tid & 63, k4 = tid >> 6;   // k4 in 0..3
            #pragma unroll
            for (int r2 = 0; r2 < 4; r2++) {
                int pl = k4 + 4 * r2;          // local plane 0..15
                float4 v = g_att4[(size_t)(kt * 16 + pl) * NPIX + pix0 + p];
                As[(pl * 4 + 0) * 64 + p] = v.x;
                As[(pl * 4 + 1) * 64 + p] = v.y;
                As[(pl * 4 + 2) * 64 + p] = v.z;
                As[(pl * 4 + 3) * 64 + p] = v.w;
            }
        }
        {
            int o = tid & 127, g = tid >> 7;   // g in 0..1
            const float4* src = (const float4*)pw + (size_t)o * 32 + kt * 16;
            #pragma unroll
            for (int r2 = 0; r2 < 8; r2++) {
                int kk = g + 2 * r2;           // 0..15
                float4 v = src[kk];
                Bs[(kk * 4 + 0) * 128 + o] = v.x;
                Bs[(kk * 4 + 1) * 128 + o] = v.y;
                Bs[(kk * 4 + 2) * 128 + o] = v.z;
                Bs[(kk * 4 + 3) * 128 + o] = v.w;
            }
        }
        __syncthreads();

        #pragma unroll 8
        for (int k = 0; k < 64; k++) {
            float4 a = ((const float4*)As)[k * 16 + tp];
            ulonglong2 b0 = ((const ulonglong2*)Bs)[k * 32 + tout * 2];
            ulonglong2 b1 = ((const ulonglong2*)Bs)[k * 32 + tout * 2 + 1];
            u64 ap[4];
            ap[0] = pk2(a.x, a.x);
            ap[1] = pk2(a.y, a.y);
            ap[2] = pk2(a.z, a.z);
            ap[3] = pk2(a.w, a.w);
            #pragma unroll
            for (int pp = 0; pp < 4; pp++) {
                acc2[pp][0] = ffma2(ap[pp], b0.x, acc2[pp][0]);
                acc2[pp][1] = ffma2(ap[pp], b0.y, acc2[pp][1]);
                acc2[pp][2] = ffma2(ap[pp], b1.x, acc2[pp][2]);
                acc2[pp][3] = ffma2(ap[pp], b1.y, acc2[pp][3]);
            }
        }
    }

    float acc[4][8];
    #pragma unroll
    for (int pp = 0; pp < 4; pp++)
        #pragma unroll
        for (int q = 0; q < 4; q++)
            upk2(acc2[pp][q], acc[pp][2 * q], acc[pp][2 * q + 1]);

    #pragma unroll
    for (int oo = 0; oo < 8; oo++) {
        int o = tout * 8 + oo;
        float bias = pb[o];
        float4 r = make_float4(acc[0][oo] + bias, acc[1][oo] + bias,
                               acc[2][oo] + bias, acc[3][oo] + bias);
        *(float4*)(out + (size_t)o * NPIX + pix0 + tp * 4) = r;
    }
}

// ---------------------------------------------------------------------------
extern "C" void kernel_launch(void* const* d_in, const int* in_sizes, int n_in,
                              void* d_out, int out_size) {
    const float* x      = (const float*)d_in[0];
    const float* qkv_w  = (const float*)d_in[1];
    const float* qkv_b  = (const float*)d_in[2];
    const float* proj_w = (const float*)d_in[3];
    const float* proj_b = (const float*)d_in[4];
    float* out = (float*)d_out;

    conv_qkv_kernel<<<384, 384>>>(x, qkv_w, qkv_b);
    attn_kernel<<<dim3(6, 6, NHEADS), 256>>>();
    proj_kernel<<<144, 256>>>(proj_w, proj_b, out);
}

// round 7
// speedup vs baseline: 1.3938x; 1.0497x over previous
#include <cuda_runtime.h>

#define HH 96
#define WW 96
#define NPIX 9216
#define NHEADS 8
#define HD 16
#define HSUB 48
#define NKEY (HSUB*HSUB)

typedef unsigned long long u64;

// Planar scratch layouts (coalesced: plane-major, pixel-minor).
// q:   plane = channel/4 (= head*4 + d/4), offset = pixel (96x96)
// k/v: plane = channel/4, offset = key (48x48 subsampled grid)
// att: plane = channel/4 (32 planes), offset = pixel
__device__ __align__(16) float4 g_q4[NHEADS * 4 * NPIX];
__device__ __align__(16) float4 g_k4[NHEADS * 4 * NKEY];
__device__ __align__(16) float4 g_v4[NHEADS * 4 * NKEY];
__device__ __align__(16) float4 g_att4[32 * NPIX];

// ---- f32x2 packed math helpers -------------------------------------------
__device__ __forceinline__ u64 pk2(float lo, float hi) {
    u64 r; asm("mov.b64 %0,{%1,%2};" : "=l"(r) : "f"(lo), "f"(hi)); return r;
}
__device__ __forceinline__ void upk2(u64 p, float& lo, float& hi) {
    asm("mov.b64 {%0,%1},%2;" : "=f"(lo), "=f"(hi) : "l"(p));
}
__device__ __forceinline__ u64 ffma2(u64 a, u64 b, u64 c) {
    u64 d; asm("fma.rn.f32x2 %0,%1,%2,%3;" : "=l"(d) : "l"(a), "l"(b), "l"(c)); return d;
}
__device__ __forceinline__ u64 fmul2(u64 a, u64 b) {
    u64 d; asm("mul.rn.f32x2 %0,%1,%2;" : "=l"(d) : "l"(a), "l"(b)); return d;
}

// ---------------------------------------------------------------------------
// Kernel 1: grouped 3x3 conv, DIRECT-LDG form (no SMEM staging).
// One thread = one float4 output quad (4 consecutive output channels at one
// output position). Grouped conv: out channel o uses input channel o/3, so a
// quad spans at most 2 input channels -> 2 predicated 3x3 windows (18 LDG,
// L1-served; warp neighbors overlap heavily). 72 FMA, 4 SEL, 1 STG.128.
// Blocks: q 1152 (32 planes x 36), k 288 (32 x 9), v 288. 256 thr each.
// ---------------------------------------------------------------------------
__global__ __launch_bounds__(256) void conv_direct_kernel(
        const float* __restrict__ x,
        const float* __restrict__ wq,
        const float* __restrict__ bq) {
    __shared__ float ws[36];
    __shared__ float bs[4];
    const int b = blockIdx.x;
    const int tid = threadIdx.x;

    int o0, i, j;
    float4* dst;
    bool isq;
    if (b < 1152) {
        const int plane = b / 36;                       // 0..31
        const int pix = (b - plane * 36) * 256 + tid;   // 0..9215
        i = pix / 96; j = pix - i * 96;
        o0 = plane * 4;
        isq = true;
        dst = g_q4 + (size_t)plane * NPIX + pix;
    } else {
        int b2 = b - 1152;
        const bool isk = b2 < 288;
        if (!isk) b2 -= 288;
        const int plane = b2 / 9;                       // 0..31
        const int key = (b2 - plane * 9) * 256 + tid;   // 0..2303
        const int gr = key / 48, gc = key - gr * 48;
        i = gr * 2; j = gc * 2;
        o0 = (isk ? 128 : 256) + plane * 4;
        isq = false;
        dst = (isk ? g_k4 : g_v4) + (size_t)plane * NKEY + key;
    }

    if (tid < 36) ws[tid] = wq[o0 * 9 + tid];
    if (tid < 4)  bs[tid] = bq[o0 + tid];
    __syncthreads();

    const int s   = 3 - (o0 % 3);   // outputs e < s use ic0, e >= s use ic0+1
    const int ic0 = o0 / 3;

    const bool up = i > 0, dn = i < 95, lf = j > 0, rt = j < 95;
    const int base = i * 96 + j;

    float accA[4], accB[4];
    #pragma unroll
    for (int pass = 0; pass < 2; pass++) {
        const float* xp = x + (size_t)(ic0 + pass) * NPIX + base;
        float v0 = (up && lf) ? xp[-97] : 0.f;
        float v1 = up         ? xp[-96] : 0.f;
        float v2 = (up && rt) ? xp[-95] : 0.f;
        float v3 = lf         ? xp[-1]  : 0.f;
        float v4 =              xp[0];
        float v5 = rt         ? xp[1]   : 0.f;
        float v6 = (dn && lf) ? xp[95]  : 0.f;
        float v7 = dn         ? xp[96]  : 0.f;
        float v8 = (dn && rt) ? xp[97]  : 0.f;
        float* acc = pass ? accB : accA;
        #pragma unroll
        for (int e = 0; e < 4; e++) {
            const float* w = ws + e * 9;
            float a = bs[e];
            a = fmaf(w[0], v0, a); a = fmaf(w[1], v1, a); a = fmaf(w[2], v2, a);
            a = fmaf(w[3], v3, a); a = fmaf(w[4], v4, a); a = fmaf(w[5], v5, a);
            a = fmaf(w[6], v6, a); a = fmaf(w[7], v7, a); a = fmaf(w[8], v8, a);
            acc[e] = a;
        }
    }

    float out[4];
    #pragma unroll
    for (int e = 0; e < 4; e++) {
        float r = (e < s) ? accA[e] : accB[e];
        out[e] = isq ? r * 0.25f : r;
    }
    *dst = make_float4(out[0], out[1], out[2], out[3]);
}

// ---------------------------------------------------------------------------
// Kernel 2: neighborhood attention, flash-style 2-chunk softmax, planar
// coalesced global loads/stores, 80B-stride SMEM tiles (conflict-free).
// grid (6,6,8): CTA = (col-tile, row-tile, head), 16x16 queries.
// ---------------------------------------------------------------------------
__global__ __launch_bounds__(256, 2) void attn_kernel() {
    __shared__ u64 Kt[256 * 10];
    __shared__ u64 Vt[256 * 10];
    const int tj = blockIdx.x, ti = blockIdx.y, n = blockIdx.z;
    const int tid = threadIdx.x;

    const int si0 = min(max(ti * 8 - 3, 0), 40);
    const int sj0 = min(max(tj * 8 - 3, 0), 40);

    {
        int kr = tid >> 4, kc = tid & 15;
        int gr = min(si0 + kr, 47);
        int gc = min(sj0 + kc, 47);
        const int key = gr * HSUB + gc;
        const ulonglong2* kg = (const ulonglong2*)g_k4 + (size_t)(n * 4) * NKEY + key;
        const ulonglong2* vg = (const ulonglong2*)g_v4 + (size_t)(n * 4) * NKEY + key;
        #pragma unroll
        for (int e = 0; e < 4; e++) {
            ulonglong2 a = kg[e * NKEY];
            Kt[tid * 10 + 2 * e]     = a.x;
            Kt[tid * 10 + 2 * e + 1] = a.y;
            ulonglong2 b = vg[e * NKEY];
            Vt[tid * 10 + 2 * e]     = b.x;
            Vt[tid * 10 + 2 * e + 1] = b.y;
        }
    }
    __syncthreads();

    const int qil = tid >> 4, qjl = tid & 15;
    const int qi = ti * 16 + qil;
    const int qj = tj * 16 + qjl;
    const int pix = qi * 96 + qj;
    const int reli = min(max((qi >> 1) - 3, 0), 40) - si0;
    const int relj = min(max((qj >> 1) - 3, 0), 40) - sj0;

    u64 qp[8];
    {
        const ulonglong2* qg = (const ulonglong2*)g_q4 + (size_t)(n * 4) * NPIX + pix;
        #pragma unroll
        for (int e = 0; e < 4; e++) {
            ulonglong2 a = qg[e * NPIX];
            qp[2 * e] = a.x; qp[2 * e + 1] = a.y;
        }
    }

    float mx = -3.4e38f;
    float sum = 0.f;
    u64 av[8];
    #pragma unroll
    for (int e = 0; e < 8; e++) av[e] = 0ull;

    #pragma unroll
    for (int ch = 0; ch < 2; ch++) {
        float lg[32];
        float cmx = -3.4e38f;
        #pragma unroll
        for (int p = 0; p < 4; p++) {
            const int rb = (reli + ch * 4 + p) * 16 + relj;
            #pragma unroll
            for (int cc = 0; cc < 8; cc++) {
                const ulonglong2* kp = (const ulonglong2*)&Kt[(rb + cc) * 10];
                ulonglong2 k0 = kp[0], k1 = kp[1], k2 = kp[2], k3 = kp[3];
                u64 acc = fmul2(qp[0], k0.x);
                acc = ffma2(qp[1], k0.y, acc);
                acc = ffma2(qp[2], k1.x, acc);
                acc = ffma2(qp[3], k1.y, acc);
                acc = ffma2(qp[4], k2.x, acc);
                acc = ffma2(qp[5], k2.y, acc);
                acc = ffma2(qp[6], k3.x, acc);
                acc = ffma2(qp[7], k3.y, acc);
                float lo, hi; upk2(acc, lo, hi);
                float s = lo + hi;
                lg[p * 8 + cc] = s;
                cmx = fmaxf(cmx, s);
            }
        }
        const float nmx = fmaxf(mx, cmx);
        const float resc = __expf(mx - nmx);   // 0 on first chunk
        sum *= resc;
        const u64 resc2 = pk2(resc, resc);
        #pragma unroll
        for (int e = 0; e < 8; e++) av[e] = fmul2(av[e], resc2);
        mx = nmx;

        #pragma unroll
        for (int k = 0; k < 32; k++) {
            float e = __expf(lg[k] - nmx);
            lg[k] = e;
            sum += e;
        }

        #pragma unroll
        for (int p = 0; p < 4; p++) {
            const int rb = (reli + ch * 4 + p) * 16 + relj;
            #pragma unroll
            for (int cc = 0; cc < 8; cc++) {
                const float wv = lg[p * 8 + cc];
                const u64 w2 = pk2(wv, wv);
                const ulonglong2* vp = (const ulonglong2*)&Vt[(rb + cc) * 10];
                ulonglong2 v0 = vp[0], v1 = vp[1], v2 = vp[2], v3 = vp[3];
                av[0] = ffma2(w2, v0.x, av[0]);
                av[1] = ffma2(w2, v0.y, av[1]);
                av[2] = ffma2(w2, v1.x, av[2]);
                av[3] = ffma2(w2, v1.y, av[3]);
                av[4] = ffma2(w2, v2.x, av[4]);
                av[5] = ffma2(w2, v2.y, av[5]);
                av[6] = ffma2(w2, v3.x, av[6]);
                av[7] = ffma2(w2, v3.y, av[7]);
            }
        }
    }

    const float inv = 1.f / sum;
    const u64 inv2 = pk2(inv, inv);
    ulonglong2* og = (ulonglong2*)g_att4 + (size_t)(n * 4) * NPIX + pix;
    #pragma unroll
    for (int e = 0; e < 4; e++) {
        ulonglong2 o;
        o.x = fmul2(av[2 * e], inv2);
        o.y = fmul2(av[2 * e + 1], inv2);
        og[e * NPIX] = o;
    }
}

// ---------------------------------------------------------------------------
// Kernel 3: 1x1 projection GEMM (f32x2 packed inner product).
// out[o][pix] = sum_c W[o][c]*att[pix][c] + b[o]
// g_att4 planar: channel c lives in plane c>>2, lane c&3 -> coalesced loads.
// CTA: 64 pixels x 128 outs, K=128 in two 64-chunks, thread tile 4 pix x 8 out.
// ---------------------------------------------------------------------------
__global__ __launch_bounds__(256) void proj_kernel(
        const float* __restrict__ pw,
        const float* __restrict__ pb,
        float* __restrict__ out) {
    __shared__ __align__(16) float As[64 * 64];    // [k][pix]
    __shared__ __align__(16) float Bs[64 * 128];   // [k][o]
    const int pix0 = blockIdx.x * 64;
    const int tid = threadIdx.x;
    const int tp = tid >> 4;       // pixel group 0..15
    const int tout = tid & 15;     // out group 0..15

    u64 acc2[4][4];
    #pragma unroll
    for (int pp = 0; pp < 4; pp++)
        #pragma unroll
        for (int q = 0; q < 4; q++) acc2[pp][q] = 0ull;

    for (int kt = 0; kt < 2; kt++) {
        __syncthreads();
        {
            int p = tid & 63, k4 = tid >> 6;   // k4 in 0..3
            #pragma unroll
            for (int r2 = 0; r2 < 4; r2++) {
                int pl = k4 + 4 * r2;          // local plane 0..15
                float4 v = g_att4[(size_t)(kt * 16 + pl) * NPIX + pix0 + p];
                As[(pl * 4 + 0) * 64 + p] = v.x;
                As[(pl * 4 + 1) * 64 + p] = v.y;
                As[(pl * 4 + 2) * 64 + p] = v.z;
                As[(pl * 4 + 3) * 64 + p] = v.w;
            }
        }
        {
            int o = tid & 127, g = tid >> 7;   // g in 0..1
            const float4* src = (const float4*)pw + (size_t)o * 32 + kt * 16;
            #pragma unroll
            for (int r2 = 0; r2 < 8; r2++) {
                int kk = g + 2 * r2;           // 0..15
                float4 v = src[kk];
                Bs[(kk * 4 + 0) * 128 + o] = v.x;
                Bs[(kk * 4 + 1) * 128 + o] = v.y;
                Bs[(kk * 4 + 2) * 128 + o] = v.z;
                Bs[(kk * 4 + 3) * 128 + o] = v.w;
            }
        }
        __syncthreads();

        #pragma unroll 8
        for (int k = 0; k < 64; k++) {
            float4 a = ((const float4*)As)[k * 16 + tp];
            ulonglong2 b0 = ((const ulonglong2*)Bs)[k * 32 + tout * 2];
            ulonglong2 b1 = ((const ulonglong2*)Bs)[k * 32 + tout * 2 + 1];
            u64 ap[4];
            ap[0] = pk2(a.x, a.x);
            ap[1] = pk2(a.y, a.y);
            ap[2] = pk2(a.z, a.z);
            ap[3] = pk2(a.w, a.w);
            #pragma unroll
            for (int pp = 0; pp < 4; pp++) {
                acc2[pp][0] = ffma2(ap[pp], b0.x, acc2[pp][0]);
                acc2[pp][1] = ffma2(ap[pp], b0.y, acc2[pp][1]);
                acc2[pp][2] = ffma2(ap[pp], b1.x, acc2[pp][2]);
                acc2[pp][3] = ffma2(ap[pp], b1.y, acc2[pp][3]);
            }
        }
    }

    float acc[4][8];
    #pragma unroll
    for (int pp = 0; pp < 4; pp++)
        #pragma unroll
        for (int q = 0; q < 4; q++)
            upk2(acc2[pp][q], acc[pp][2 * q], acc[pp][2 * q + 1]);

    #pragma unroll
    for (int oo = 0; oo < 8; oo++) {
        int o = tout * 8 + oo;
        float bias = pb[o];
        float4 r = make_float4(acc[0][oo] + bias, acc[1][oo] + bias,
                               acc[2][oo] + bias, acc[3][oo] + bias);
        *(float4*)(out + (size_t)o * NPIX + pix0 + tp * 4) = r;
    }
}

// ---------------------------------------------------------------------------
extern "C" void kernel_launch(void* const* d_in, const int* in_sizes, int n_in,
                              void* d_out, int out_size) {
    const float* x      = (const float*)d_in[0];
    const float* qkv_w  = (const float*)d_in[1];
    const float* qkv_b  = (const float*)d_in[2];
    const float* proj_w = (const float*)d_in[3];
    const float* proj_b = (const float*)d_in[4];
    float* out = (float*)d_out;

    conv_direct_kernel<<<1728, 256>>>(x, qkv_w, qkv_b);
    attn_kernel<<<dim3(6, 6, NHEADS), 256>>>();
    proj_kernel<<<144, 256>>>(proj_w, proj_b, out);
}